// round 1
// baseline (speedup 1.0000x reference)
#include <cuda_runtime.h>
#include <cstdint>

#define NQ 8
#define INDIM 512
#define FULLMASK 0xffffffffu

// Precomputed per-launch constants (setup kernel writes, main kernel reads).
__device__ float4 d_Wg4[NQ * (INDIM / 4)];  // gamma ⊙ W_pre, [8][512] as float4
__device__ float  d_Sg[NQ];                 // sum_k gamma_k W[q,k]
__device__ float  d_Cq[NQ];                 // sum_k beta_k W[q,k] + b_pre[q]
__device__ float  d_gT[256];                // g table, transposed: idx = r*8 + l, b = r | (l<<5)
__device__ float  d_ct[NQ], d_st[NQ];       // cos/sin(theta/2)
__device__ float  d_bpost;

__global__ void setup_kernel(const float* __restrict__ ln_gamma,
                             const float* __restrict__ ln_beta,
                             const float* __restrict__ W_pre,
                             const float* __restrict__ b_pre,
                             const float* __restrict__ theta,
                             const float* __restrict__ W_post,
                             const float* __restrict__ b_post) {
    int tid = threadIdx.x;
    float* Wg = (float*)d_Wg4;
    for (int idx = tid; idx < NQ * INDIM; idx += 256) {
        int k = idx & (INDIM - 1);
        Wg[idx] = ln_gamma[k] * W_pre[idx];
    }
    if (tid < NQ) {
        float sg = 0.f, c = 0.f;
        for (int k = 0; k < INDIM; k++) {
            float w = W_pre[tid * INDIM + k];
            sg += ln_gamma[k] * w;
            c  += ln_beta[k] * w;
        }
        d_Sg[tid] = sg;
        d_Cq[tid] = c + b_pre[tid];
        float h = 0.5f * theta[tid];
        d_ct[tid] = cosf(h);
        d_st[tid] = sinf(h);
    }
    // g table: b bits: qubits 0-4 = r, qubits 5-7 = l. Stored at r*8+l.
    {
        int r = tid >> 3, l = tid & 7;
        int b = r | (l << 5);
        float g = 0.f;
        for (int i = 0; i < NQ; i++)
            g += W_post[i] * (((b >> i) & 1) ? -1.f : 1.f);
        d_gT[tid] = g;
    }
    if (tid == 0) d_bpost = b_post[0];
}

// 8 lanes per row (lane bits l = qubits 5..7), 32 amplitudes per thread
// (reg bits r = qubits 0..4). 4 rows per warp. Bit i of basis index b = qubit i.
__global__ __launch_bounds__(256) void qsco_kernel(const float* __restrict__ E,
                                                   float* __restrict__ out,
                                                   int B) {
    __shared__ float4 sWg4[NQ * (INDIM / 4)];  // 16 KB
    __shared__ float  sGT[256];                // 1 KB

    int tid = threadIdx.x;
    for (int i = tid; i < NQ * (INDIM / 4); i += 256) sWg4[i] = d_Wg4[i];
    sGT[tid] = d_gT[tid];
    __syncthreads();

    int lane = tid & 31;
    int grp  = lane >> 3;        // which of 4 rows in this warp
    int l    = lane & 7;         // sub-lane = qubit bits 5..7
    int warp = (blockIdx.x * 256 + tid) >> 5;
    int row  = warp * 4 + grp;
    int row_c = row < B ? row : (B - 1);

    // ---- Pass over E: sum, sumsq, 8 dots with Wg (LN folded into linear) ----
    const float4* Erow = (const float4*)(E + (size_t)row_c * INDIM);
    float s = 0.f, ss = 0.f;
    float acc[NQ];
    #pragma unroll
    for (int q = 0; q < NQ; q++) acc[q] = 0.f;

    #pragma unroll
    for (int i = 0; i < 16; i++) {
        float4 e = Erow[l + 8 * i];
        s  += (e.x + e.y) + (e.z + e.w);
        ss = fmaf(e.x, e.x, ss); ss = fmaf(e.y, e.y, ss);
        ss = fmaf(e.z, e.z, ss); ss = fmaf(e.w, e.w, ss);
        #pragma unroll
        for (int q = 0; q < NQ; q++) {
            float4 w = sWg4[q * 128 + l + 8 * i];
            float a = acc[q];
            a = fmaf(e.x, w.x, a); a = fmaf(e.y, w.y, a);
            a = fmaf(e.z, w.z, a); a = fmaf(e.w, w.w, a);
            acc[q] = a;
        }
    }
    // reduce 10 values across the 8-lane group
    #pragma unroll
    for (int m = 1; m < 8; m <<= 1) {
        s  += __shfl_xor_sync(FULLMASK, s, m);
        ss += __shfl_xor_sync(FULLMASK, ss, m);
        #pragma unroll
        for (int q = 0; q < NQ; q++)
            acc[q] += __shfl_xor_sync(FULLMASK, acc[q], m);
    }

    const float inv512 = 1.0f / 512.0f;
    float mu  = s * inv512;
    float var = fmaf(-mu, mu, ss * inv512);
    float inv = rsqrtf(var + 1e-5f);

    float ca[NQ], sa[NQ];
    #pragma unroll
    for (int q = 0; q < NQ; q++) {
        float ang = fmaf(inv, fmaf(-mu, d_Sg[q], acc[q]), d_Cq[q]);
        __sincosf(0.5f * ang, &sa[q], &ca[q]);
    }

    float ct[NQ], st[NQ];
    #pragma unroll
    for (int q = 0; q < NQ; q++) { ct[q] = d_ct[q]; st[q] = d_st[q]; }

    // ---- Initial product state ----
    float amp[32];
    float w5 = (l & 1) ? sa[5] : ca[5];
    float w6 = (l & 2) ? sa[6] : ca[6];
    float w7 = (l & 4) ? sa[7] : ca[7];
    amp[0] = w5 * w6 * w7;
    #pragma unroll
    for (int q = 0; q < 5; q++) {
        const int cnt = 1 << q;
        #pragma unroll
        for (int r = 0; r < 16; r++) {
            if (r < cnt) {
                amp[r + cnt] = amp[r] * sa[q];
                amp[r]       = amp[r] * ca[q];
            }
        }
    }

    // precomputed signs for lane-RYs (sgn = +s if my target bit is 1 else -s)
    float sg5 = (l & 1) ? st[5] : -st[5];
    float sg6 = (l & 2) ? st[6] : -st[6];
    float sg7 = (l & 4) ? st[7] : -st[7];
    int ctrl5 = l & 1;          // qubit5 value (lane bit 0)
    int ctrl6 = (l >> 1) & 1;   // qubit6
    int ctrl7 = (l >> 2) & 1;   // qubit7

    // ---- DEPTH=2: CNOT ring 0->1->...->7->0, then RY(theta) on all qubits ----
    #pragma unroll
    for (int d = 0; d < 2; d++) {
        // CNOT(0,1): reg-reg
        #pragma unroll
        for (int r = 0; r < 32; r++)
            if ((r & 1) && !(r & 2)) { float t = amp[r]; amp[r] = amp[r | 2]; amp[r | 2] = t; }
        // CNOT(1,2)
        #pragma unroll
        for (int r = 0; r < 32; r++)
            if ((r & 2) && !(r & 4)) { float t = amp[r]; amp[r] = amp[r | 4]; amp[r | 4] = t; }
        // CNOT(2,3)
        #pragma unroll
        for (int r = 0; r < 32; r++)
            if ((r & 4) && !(r & 8)) { float t = amp[r]; amp[r] = amp[r | 8]; amp[r | 8] = t; }
        // CNOT(3,4)
        #pragma unroll
        for (int r = 0; r < 32; r++)
            if ((r & 8) && !(r & 16)) { float t = amp[r]; amp[r] = amp[r | 16]; amp[r | 16] = t; }
        // CNOT(4,5): control reg bit4, target lane bit0 -> swap those regs across lane^1
        #pragma unroll
        for (int r = 16; r < 32; r++)
            amp[r] = __shfl_xor_sync(FULLMASK, amp[r], 1);
        // CNOT(5,6): control lane bit0, target lane bit1
        #pragma unroll
        for (int r = 0; r < 32; r++) {
            float p = __shfl_xor_sync(FULLMASK, amp[r], 2);
            amp[r] = ctrl5 ? p : amp[r];
        }
        // CNOT(6,7): control lane bit1, target lane bit2
        #pragma unroll
        for (int r = 0; r < 32; r++) {
            float p = __shfl_xor_sync(FULLMASK, amp[r], 4);
            amp[r] = ctrl6 ? p : amp[r];
        }
        // CNOT(7,0): control lane bit2, target reg bit0 -> conditional reg swap
        #pragma unroll
        for (int r = 0; r < 32; r += 2) {
            float a0 = amp[r], a1 = amp[r + 1];
            amp[r]     = ctrl7 ? a1 : a0;
            amp[r + 1] = ctrl7 ? a0 : a1;
        }
        // RY(theta_q) on register qubits 0..4
        #pragma unroll
        for (int q = 0; q < 5; q++) {
            const int bq = 1 << q;
            float c = ct[q], sv = st[q];
            #pragma unroll
            for (int r = 0; r < 32; r++) {
                if (!(r & bq)) {
                    int r2 = r | bq;
                    float a0 = amp[r], a1 = amp[r2];
                    amp[r]  = fmaf(-sv, a1, c * a0);
                    amp[r2] = fmaf(sv, a0, c * a1);
                }
            }
        }
        // RY(theta) on lane qubits 5,6,7
        #pragma unroll
        for (int r = 0; r < 32; r++) {
            float p = __shfl_xor_sync(FULLMASK, amp[r], 1);
            amp[r] = fmaf(sg5, p, ct[5] * amp[r]);
        }
        #pragma unroll
        for (int r = 0; r < 32; r++) {
            float p = __shfl_xor_sync(FULLMASK, amp[r], 2);
            amp[r] = fmaf(sg6, p, ct[6] * amp[r]);
        }
        #pragma unroll
        for (int r = 0; r < 32; r++) {
            float p = __shfl_xor_sync(FULLMASK, amp[r], 4);
            amp[r] = fmaf(sg7, p, ct[7] * amp[r]);
        }
    }

    // ---- Readout: logit = sum_b amp_b^2 * g_b + b_post ----
    float tot = 0.f;
    #pragma unroll
    for (int r = 0; r < 32; r++) {
        float p = amp[r] * amp[r];
        tot = fmaf(p, sGT[r * 8 + l], tot);
    }
    #pragma unroll
    for (int m = 1; m < 8; m <<= 1)
        tot += __shfl_xor_sync(FULLMASK, tot, m);

    if (l == 0 && row < B)
        out[row] = tot + d_bpost;
}

extern "C" void kernel_launch(void* const* d_in, const int* in_sizes, int n_in,
                              void* d_out, int out_size) {
    const float* E        = (const float*)d_in[0];
    const float* ln_gamma = (const float*)d_in[1];
    const float* ln_beta  = (const float*)d_in[2];
    const float* W_pre    = (const float*)d_in[3];
    const float* b_pre    = (const float*)d_in[4];
    const float* theta    = (const float*)d_in[5];
    const float* W_post   = (const float*)d_in[6];
    const float* b_post   = (const float*)d_in[7];
    float* out = (float*)d_out;
    int B = out_size;

    setup_kernel<<<1, 256>>>(ln_gamma, ln_beta, W_pre, b_pre, theta, W_post, b_post);

    // 32 rows per 256-thread block (4 rows/warp)
    int grid = (B + 31) / 32;
    qsco_kernel<<<grid, 256>>>(E, out, B);
}

// round 3
// speedup vs baseline: 1.8145x; 1.8145x over previous
#include <cuda_runtime.h>
#include <cstdint>

#define FULLMASK 0xffffffffu

// Precomputed constants
__device__ float4 d_Wg4[8 * 128];   // gamma ⊙ W_pre, [8][512] as float4
__device__ float  d_Sg[8];          // sum_k gamma_k W[q,k]
__device__ float  d_Cq[8];          // sum_k beta_k W[q,k] + b_pre[q]
__device__ float  d_gT[4 * 68];     // g table: [lsub][r] padded stride 68, b = r | (lsub<<6)
__device__ float  d_ct[8], d_st[8]; // cos/sin(theta/2)
__device__ float  d_bpost;

__global__ void setup_kernel(const float* __restrict__ ln_gamma,
                             const float* __restrict__ ln_beta,
                             const float* __restrict__ W_pre,
                             const float* __restrict__ b_pre,
                             const float* __restrict__ theta,
                             const float* __restrict__ W_post,
                             const float* __restrict__ b_post) {
    int tid = threadIdx.x;
    int lane = tid & 31;
    int wrp = tid >> 5;  // 8 warps
    float* Wg = (float*)d_Wg4;
    for (int idx = tid; idx < 8 * 512; idx += 256) {
        int k = idx & 511;
        Wg[idx] = ln_gamma[k] * W_pre[idx];
    }
    // warp w handles qubit q = w
    {
        int q = wrp;
        float sg = 0.f, c = 0.f;
        for (int k = lane; k < 512; k += 32) {
            float wv = W_pre[q * 512 + k];
            sg += ln_gamma[k] * wv;
            c += ln_beta[k] * wv;
        }
        #pragma unroll
        for (int m = 16; m; m >>= 1) {
            sg += __shfl_xor_sync(FULLMASK, sg, m);
            c  += __shfl_xor_sync(FULLMASK, c, m);
        }
        if (lane == 0) {
            d_Sg[q] = sg;
            d_Cq[q] = c + b_pre[q];
            float h = 0.5f * theta[q];
            d_ct[q] = cosf(h);
            d_st[q] = sinf(h);
        }
    }
    // g table: 256 entries, padded layout [lsub*68 + r]
    {
        int lsub = tid >> 6, r = tid & 63;
        int b = r | (lsub << 6);
        float g = 0.f;
        #pragma unroll
        for (int i = 0; i < 8; i++)
            g += W_post[i] * (((b >> i) & 1) ? -1.f : 1.f);
        d_gT[lsub * 68 + r] = g;
    }
    if (tid == 0) d_bpost = b_post[0];
}

// Layout: 4 lanes per row (lane bit0 = qubit6, bit1 = qubit7), 64 amps/thread
// (amp index bits 0..5 = qubits 0..5). 8 rows per warp.
// Phase 1 computes 8 rows' angles cooperatively (full warp, 2 chunks of 4 rows)
// with weight LDS amortized 4x; routed reduction lands each row at its 4 lanes.
__global__ __launch_bounds__(256) void qsco_kernel(const float* __restrict__ E,
                                                   float* __restrict__ out,
                                                   int B) {
    __shared__ float4 sWg4[8 * 128];            // 16 KB
    __shared__ __align__(16) float sGT[4 * 68]; // ~1.1 KB

    int tid = threadIdx.x;
    for (int i = tid; i < 1024; i += 256) sWg4[i] = d_Wg4[i];
    for (int i = tid; i < 272; i += 256) sGT[i] = d_gT[i];   // FIX: full 272-entry copy
    __syncthreads();

    int lane = tid & 31;
    int warp = (blockIdx.x * 256 + tid) >> 5;
    int warp_row0 = warp * 8;

    // ---------------- Phase 1: angles for 8 rows per warp ----------------
    // W[c][k]: chunk c (rows 4c..4c+3), this thread ends with row (lane>>3)'s
    // sums. k: 0=sum, 1=sumsq, 2..9 = dot with Wg[q].
    float Wv[2][10];

    #pragma unroll
    for (int c = 0; c < 2; c++) {
        float V[4][10];
        #pragma unroll
        for (int rr = 0; rr < 4; rr++)
            #pragma unroll
            for (int k = 0; k < 10; k++) V[rr][k] = 0.f;

        const float4* er[4];
        #pragma unroll
        for (int rr = 0; rr < 4; rr++) {
            int r = warp_row0 + c * 4 + rr;
            if (r >= B) r = B - 1;
            er[rr] = (const float4*)(E + (size_t)r * 512);
        }

        #pragma unroll
        for (int j = 0; j < 4; j++) {
            float4 e[4];
            #pragma unroll
            for (int rr = 0; rr < 4; rr++) e[rr] = er[rr][j * 32 + lane];
            #pragma unroll
            for (int rr = 0; rr < 4; rr++) {
                V[rr][0] += (e[rr].x + e[rr].y) + (e[rr].z + e[rr].w);
                float ssv = V[rr][1];
                ssv = fmaf(e[rr].x, e[rr].x, ssv);
                ssv = fmaf(e[rr].y, e[rr].y, ssv);
                ssv = fmaf(e[rr].z, e[rr].z, ssv);
                ssv = fmaf(e[rr].w, e[rr].w, ssv);
                V[rr][1] = ssv;
            }
            #pragma unroll
            for (int q = 0; q < 8; q++) {
                float4 wv = sWg4[q * 128 + j * 32 + lane];
                #pragma unroll
                for (int rr = 0; rr < 4; rr++) {
                    float a = V[rr][2 + q];
                    a = fmaf(e[rr].x, wv.x, a);
                    a = fmaf(e[rr].y, wv.y, a);
                    a = fmaf(e[rr].z, wv.z, a);
                    a = fmaf(e[rr].w, wv.w, a);
                    V[rr][2 + q] = a;
                }
            }
        }

        // Routed reduction:
        // stage xor16: full butterfly on all 4 rows
        #pragma unroll
        for (int rr = 0; rr < 4; rr++)
            #pragma unroll
            for (int k = 0; k < 10; k++)
                V[rr][k] += __shfl_xor_sync(FULLMASK, V[rr][k], 16);
        // upper half keeps rows 2,3 in slots 0,1
        bool up = (lane & 16) != 0;
        #pragma unroll
        for (int k = 0; k < 10; k++) {
            V[0][k] = up ? V[2][k] : V[0][k];
            V[1][k] = up ? V[3][k] : V[1][k];
        }
        // stage xor8 on the two surviving slots
        #pragma unroll
        for (int k = 0; k < 10; k++) {
            V[0][k] += __shfl_xor_sync(FULLMASK, V[0][k], 8);
            V[1][k] += __shfl_xor_sync(FULLMASK, V[1][k], 8);
        }
        // select my octet's row, finish xor4/2/1
        bool sel1 = (lane & 8) != 0;
        #pragma unroll
        for (int k = 0; k < 10; k++) {
            float v = sel1 ? V[1][k] : V[0][k];
            v += __shfl_xor_sync(FULLMASK, v, 4);
            v += __shfl_xor_sync(FULLMASK, v, 2);
            v += __shfl_xor_sync(FULLMASK, v, 1);
            Wv[c][k] = v;
        }
    }

    // Group g = lane>>2 simulates: even g -> chunk0 row (lane>>3), odd g -> chunk1 row (lane>>3)
    int use1 = (lane >> 2) & 1;
    float A[10];
    #pragma unroll
    for (int k = 0; k < 10; k++) A[k] = use1 ? Wv[1][k] : Wv[0][k];
    int myrow = warp_row0 + use1 * 4 + (lane >> 3);

    const float inv512 = 1.0f / 512.0f;
    float mu = A[0] * inv512;
    float var = fmaf(-mu, mu, A[1] * inv512);
    float inv = rsqrtf(var + 1e-5f);

    float ca[8], sa[8], ct[8], st[8];
    #pragma unroll
    for (int q = 0; q < 8; q++) {
        float ang = fmaf(inv, fmaf(-mu, d_Sg[q], A[2 + q]), d_Cq[q]);
        __sincosf(0.5f * ang, &sa[q], &ca[q]);
        ct[q] = d_ct[q];
        st[q] = d_st[q];
    }

    // ---------------- Phase 2: circuit, 64 amps/thread ----------------
    int b6 = lane & 1;
    int b7 = (lane >> 1) & 1;
    int lbase = lane & ~3;
    // merged CNOT(5,6)+(6,7) source lanes
    int s0 = lbase | b6 | ((b7 ^ b6) << 1);  // regs with bit5=0
    int s1 = s0 ^ 1;                          // regs with bit5=1
    float sg6 = b6 ? st[6] : -st[6];
    float sg7 = b7 ? st[7] : -st[7];
    // fused CNOT(7,0)+RY(0) coefficients (control = qubit7 = b7)
    float k00 = b7 ? -st[0] : ct[0];
    float k01 = b7 ? ct[0] : -st[0];
    float k10 = b7 ? ct[0] : st[0];
    float k11 = b7 ? st[0] : ct[0];

    float amp[64];
    {
        float w6 = b6 ? sa[6] : ca[6];
        float w7 = b7 ? sa[7] : ca[7];
        amp[0] = w6 * w7;
        #pragma unroll
        for (int q = 0; q < 6; q++) {
            const int cnt = 1 << q;
            #pragma unroll
            for (int r = 0; r < 32; r++) {
                if (r < cnt) {
                    amp[r + cnt] = amp[r] * sa[q];
                    amp[r]       = amp[r] * ca[q];
                }
            }
        }
    }

    #pragma unroll
    for (int d = 0; d < 2; d++) {
        // CNOT(0,1)..(4,5): static register permutations (compile-time swaps)
        #pragma unroll
        for (int r = 0; r < 64; r++)
            if ((r & 1) && !(r & 2)) { float t = amp[r]; amp[r] = amp[r | 2]; amp[r | 2] = t; }
        #pragma unroll
        for (int r = 0; r < 64; r++)
            if ((r & 2) && !(r & 4)) { float t = amp[r]; amp[r] = amp[r | 4]; amp[r | 4] = t; }
        #pragma unroll
        for (int r = 0; r < 64; r++)
            if ((r & 4) && !(r & 8)) { float t = amp[r]; amp[r] = amp[r | 8]; amp[r | 8] = t; }
        #pragma unroll
        for (int r = 0; r < 64; r++)
            if ((r & 8) && !(r & 16)) { float t = amp[r]; amp[r] = amp[r | 16]; amp[r | 16] = t; }
        #pragma unroll
        for (int r = 0; r < 64; r++)
            if ((r & 16) && !(r & 32)) { float t = amp[r]; amp[r] = amp[r | 32]; amp[r | 32] = t; }
        // merged CNOT(5,6)+CNOT(6,7): one idx-shuffle per reg
        #pragma unroll
        for (int r = 0; r < 64; r++)
            amp[r] = __shfl_sync(FULLMASK, amp[r], (r & 32) ? s1 : s0);
        // fused CNOT(7,0)+RY(0) on pairs (2m, 2m+1)
        #pragma unroll
        for (int r = 0; r < 64; r += 2) {
            float a0 = amp[r], a1 = amp[r + 1];
            amp[r]     = fmaf(k00, a0, k01 * a1);
            amp[r + 1] = fmaf(k10, a0, k11 * a1);
        }
        // RY on reg qubits 1..5
        #pragma unroll
        for (int q = 1; q < 6; q++) {
            const int bq = 1 << q;
            float cc = ct[q], sv = st[q];
            #pragma unroll
            for (int r = 0; r < 64; r++) {
                if (!(r & bq)) {
                    int r2 = r | bq;
                    float a0 = amp[r], a1 = amp[r2];
                    amp[r]  = fmaf(-sv, a1, cc * a0);
                    amp[r2] = fmaf(sv, a0, cc * a1);
                }
            }
        }
        // RY(6): lane xor1
        #pragma unroll
        for (int r = 0; r < 64; r++) {
            float p = __shfl_xor_sync(FULLMASK, amp[r], 1);
            amp[r] = fmaf(sg6, p, ct[6] * amp[r]);
        }
        // RY(7): lane xor2
        #pragma unroll
        for (int r = 0; r < 64; r++) {
            float p = __shfl_xor_sync(FULLMASK, amp[r], 2);
            amp[r] = fmaf(sg7, p, ct[7] * amp[r]);
        }
    }

    // ---------------- Readout ----------------
    float tot = 0.f;
    int lsub = lane & 3;
    #pragma unroll
    for (int j = 0; j < 16; j++) {
        float4 g4 = *(const float4*)&sGT[lsub * 68 + 4 * j];
        tot = fmaf(amp[4 * j + 0] * amp[4 * j + 0], g4.x, tot);
        tot = fmaf(amp[4 * j + 1] * amp[4 * j + 1], g4.y, tot);
        tot = fmaf(amp[4 * j + 2] * amp[4 * j + 2], g4.z, tot);
        tot = fmaf(amp[4 * j + 3] * amp[4 * j + 3], g4.w, tot);
    }
    tot += __shfl_xor_sync(FULLMASK, tot, 1);
    tot += __shfl_xor_sync(FULLMASK, tot, 2);

    if (lsub == 0 && myrow < B)
        out[myrow] = tot + d_bpost;
}

extern "C" void kernel_launch(void* const* d_in, const int* in_sizes, int n_in,
                              void* d_out, int out_size) {
    const float* E        = (const float*)d_in[0];
    const float* ln_gamma = (const float*)d_in[1];
    const float* ln_beta  = (const float*)d_in[2];
    const float* W_pre    = (const float*)d_in[3];
    const float* b_pre    = (const float*)d_in[4];
    const float* theta    = (const float*)d_in[5];
    const float* W_post   = (const float*)d_in[6];
    const float* b_post   = (const float*)d_in[7];
    float* out = (float*)d_out;
    int B = out_size;

    setup_kernel<<<1, 256>>>(ln_gamma, ln_beta, W_pre, b_pre, theta, W_post, b_post);

    // 64 rows per 256-thread block (8 rows/warp)
    int grid = (B + 63) / 64;
    qsco_kernel<<<grid, 256>>>(E, out, B);
}